// round 2
// baseline (speedup 1.0000x reference)
#include <cuda_runtime.h>
#include <math.h>

#define T_LEN   2048
#define HIDDEN  4096
#define NH      32
#define HD      128
#define QSIZE   (NH*HD)          // 4096
#define QKV_OUT 12288            // q(4096) + k(4096) + v(4096)
#define EPS     1e-5f
#define ROPE_THETA 1000000.0f

// Scratch (static device globals: allocation-free per harness rules)
__device__ float g_qkv[(size_t)T_LEN * QKV_OUT];    // ~100 MB
__device__ float g_attn[(size_t)T_LEN * QSIZE];     // ~33 MB

// ---------------------------------------------------------------------------
// SGEMM: C[m][n] = sum_k A[m][k] * B[n][k] (+ bias[n])
// A: [M,K] row-major, B: [N,K] row-major (both K-contiguous).
// BM=BN=128, BK=16, 256 threads, 8x8 per-thread micro-tile.
// ---------------------------------------------------------------------------
template<bool HAS_BIAS>
__global__ __launch_bounds__(256, 2)
void sgemm_nt(const float* __restrict__ A, const float* __restrict__ B,
              const float* __restrict__ bias, float* __restrict__ C,
              int M, int N, int K)
{
    const int BM = 128, BN = 128, BK = 16;
    __shared__ float As[BK][BM + 8];
    __shared__ float Bs[BK][BN + 8];

    const int tid = threadIdx.x;
    const int tx = tid & 15;          // 0..15 -> n
    const int ty = tid >> 4;          // 0..15 -> m
    const int bm = blockIdx.y * BM;
    const int bn = blockIdx.x * BN;

    float acc[8][8];
    #pragma unroll
    for (int i = 0; i < 8; i++)
        #pragma unroll
        for (int j = 0; j < 8; j++) acc[i][j] = 0.f;

    for (int k0 = 0; k0 < K; k0 += BK) {
        // Load A and B tiles (transposed into smem), 2 float4 each
        #pragma unroll
        for (int it = 0; it < 2; it++) {
            int f  = tid + it * 256;          // 0..511
            int m  = f >> 2;                  // 0..127
            int kq = (f & 3) << 2;            // 0,4,8,12
            float4 va = *(const float4*)&A[(size_t)(bm + m) * K + k0 + kq];
            As[kq + 0][m] = va.x; As[kq + 1][m] = va.y;
            As[kq + 2][m] = va.z; As[kq + 3][m] = va.w;
            float4 vb = *(const float4*)&B[(size_t)(bn + m) * K + k0 + kq];
            Bs[kq + 0][m] = vb.x; Bs[kq + 1][m] = vb.y;
            Bs[kq + 2][m] = vb.z; Bs[kq + 3][m] = vb.w;
        }
        __syncthreads();

        #pragma unroll
        for (int kk = 0; kk < BK; kk++) {
            float a[8], b[8];
            #pragma unroll
            for (int i = 0; i < 8; i++) a[i] = As[kk][ty * 8 + i];
            #pragma unroll
            for (int j = 0; j < 8; j++) b[j] = Bs[kk][tx * 8 + j];
            #pragma unroll
            for (int i = 0; i < 8; i++)
                #pragma unroll
                for (int j = 0; j < 8; j++) acc[i][j] += a[i] * b[j];
        }
        __syncthreads();
    }

    #pragma unroll
    for (int i = 0; i < 8; i++) {
        int m = bm + ty * 8 + i;
        #pragma unroll
        for (int j0 = 0; j0 < 8; j0 += 4) {
            int n = bn + tx * 8 + j0;
            float4 v;
            v.x = acc[i][j0 + 0]; v.y = acc[i][j0 + 1];
            v.z = acc[i][j0 + 2]; v.w = acc[i][j0 + 3];
            if (HAS_BIAS) {
                v.x += bias[n + 0]; v.y += bias[n + 1];
                v.z += bias[n + 2]; v.w += bias[n + 3];
            }
            *(float4*)&C[(size_t)m * N + n] = v;
        }
    }
}

// ---------------------------------------------------------------------------
// Per-token: RMSNorm over full q (4096) and k (4096) slices, then RoPE
// per head (in place on g_qkv). One block per token, 256 threads.
// ---------------------------------------------------------------------------
__global__ void norm_rope_kernel(const int* __restrict__ positions,
                                 const float* __restrict__ qw,
                                 const float* __restrict__ kw)
{
    const int t   = blockIdx.x;
    const int tid = threadIdx.x;
    float* row = g_qkv + (size_t)t * QKV_OUT;

    __shared__ float red[256];
    __shared__ float s_scale_q, s_scale_k;

    float sq = 0.f, sk = 0.f;
    for (int i = tid; i < QSIZE; i += 256) {
        float x = row[i];         sq += x * x;
        float y = row[QSIZE + i]; sk += y * y;
    }

    red[tid] = sq; __syncthreads();
    for (int s = 128; s > 0; s >>= 1) {
        if (tid < s) red[tid] += red[tid + s];
        __syncthreads();
    }
    if (tid == 0) s_scale_q = rsqrtf(red[0] * (1.0f / QSIZE) + EPS);
    __syncthreads();

    red[tid] = sk; __syncthreads();
    for (int s = 128; s > 0; s >>= 1) {
        if (tid < s) red[tid] += red[tid + s];
        __syncthreads();
    }
    if (tid == 0) s_scale_k = rsqrtf(red[0] * (1.0f / QSIZE) + EPS);
    __syncthreads();

    const float scq = s_scale_q, sck = s_scale_k;
    const float pos = (float)positions[t];

    // 32 heads * 64 (d,d+64) pairs = 2048 work items
    for (int idx = tid; idx < NH * 64; idx += 256) {
        int h = idx >> 6;
        int d = idx & 63;
        float inv_freq = powf(ROPE_THETA, -(float)d * (1.0f / 64.0f));
        float ang = pos * inv_freq;
        float sn, cs;
        sincosf(ang, &sn, &cs);

        int off = h * HD;
        // q
        {
            float x1 = row[off + d]      * scq * qw[off + d];
            float x2 = row[off + 64 + d] * scq * qw[off + 64 + d];
            row[off + d]      = x1 * cs - x2 * sn;
            row[off + 64 + d] = x2 * cs + x1 * sn;
        }
        // k
        {
            int offk = QSIZE + off;
            float x1 = row[offk + d]      * sck * kw[off + d];
            float x2 = row[offk + 64 + d] * sck * kw[off + 64 + d];
            row[offk + d]      = x1 * cs - x2 * sn;
            row[offk + 64 + d] = x2 * cs + x1 * sn;
        }
    }
}

// ---------------------------------------------------------------------------
// Flash-style causal attention, fp32.
// Grid: (T/64, NH). 256 threads: 64 rows x 4 lanes/row.
// Lane c owns dims d = c + 4*u (u in 0..31)  -> conflict-free smem access.
// Lane c computes score columns j = c + 4*jj (jj in 0..15).
// ---------------------------------------------------------------------------
#define AT_BM 64
#define AT_BN 64
#define QK_STRIDE 132   // 128 + 4 (float4 aligned, conflict-free)
#define SS_STRIDE 68

__global__ __launch_bounds__(256, 1)
void attn_kernel()
{
    extern __shared__ float smem[];
    float* Qs = smem;                          // [64][132]
    float* Ks = Qs + AT_BM * QK_STRIDE;        // [64][132]
    float* Vs = Ks + AT_BN * QK_STRIDE;        // [64][132]
    float* Ss = Vs + AT_BN * QK_STRIDE;        // [64][68]

    const int qb  = blockIdx.x;
    const int h   = blockIdx.y;
    const int tid = threadIdx.x;
    const int r   = tid >> 2;   // 0..63
    const int c   = tid & 3;    // 0..3
    const float scale = 0.08838834764831845f;  // 1/sqrt(128)

    // Load Q tile
    for (int f = tid; f < AT_BM * 32; f += 256) {
        int m  = f >> 5;
        int dq = (f & 31) << 2;
        *(float4*)&Qs[m * QK_STRIDE + dq] =
            *(const float4*)&g_qkv[(size_t)(qb * AT_BM + m) * QKV_OUT + h * HD + dq];
    }

    float O[32];
    #pragma unroll
    for (int u = 0; u < 32; u++) O[u] = 0.f;
    float mrow = -1e30f, lrow = 0.f;

    const int qpos = qb * AT_BM + r;
    const int ntiles = qb + 1;

    for (int kb = 0; kb < ntiles; kb++) {
        __syncthreads();
        // Load K and V tiles
        for (int f = tid; f < AT_BN * 32; f += 256) {
            int m  = f >> 5;
            int dq = (f & 31) << 2;
            size_t gb = (size_t)(kb * AT_BN + m) * QKV_OUT + h * HD + dq;
            *(float4*)&Ks[m * QK_STRIDE + dq] = *(const float4*)&g_qkv[gb + QSIZE];
            *(float4*)&Vs[m * QK_STRIDE + dq] = *(const float4*)&g_qkv[gb + 2 * QSIZE];
        }
        __syncthreads();

        // S = Q K^T for keys j = c + 4*jj
        float s[16];
        #pragma unroll
        for (int jj = 0; jj < 16; jj++) s[jj] = 0.f;

        for (int d = 0; d < HD; d += 4) {
            float4 qv = *(float4*)&Qs[r * QK_STRIDE + d];
            #pragma unroll
            for (int jj = 0; jj < 16; jj++) {
                int j = c + 4 * jj;
                float4 kv = *(float4*)&Ks[j * QK_STRIDE + d];
                s[jj] += qv.x * kv.x + qv.y * kv.y + qv.z * kv.z + qv.w * kv.w;
            }
        }

        // scale + causal mask + row max
        float tmax = -1e30f;
        #pragma unroll
        for (int jj = 0; jj < 16; jj++) {
            int kpos = kb * AT_BN + c + 4 * jj;
            s[jj] = (kpos <= qpos) ? s[jj] * scale : -1e30f;
            tmax = fmaxf(tmax, s[jj]);
        }
        tmax = fmaxf(tmax, __shfl_xor_sync(0xffffffffu, tmax, 1));
        tmax = fmaxf(tmax, __shfl_xor_sync(0xffffffffu, tmax, 2));

        float mnew = fmaxf(mrow, tmax);
        float psum = 0.f;
        #pragma unroll
        for (int jj = 0; jj < 16; jj++) {
            float p = __expf(s[jj] - mnew);
            Ss[r * SS_STRIDE + c + 4 * jj] = p;
            psum += p;
        }
        psum += __shfl_xor_sync(0xffffffffu, psum, 1);
        psum += __shfl_xor_sync(0xffffffffu, psum, 2);

        float alpha = __expf(mrow - mnew);
        lrow = lrow * alpha + psum;
        mrow = mnew;
        #pragma unroll
        for (int u = 0; u < 32; u++) O[u] *= alpha;

        __syncthreads();

        // O += P V  (lane c owns dims c + 4u)
        for (int j = 0; j < AT_BN; j++) {
            float p = Ss[r * SS_STRIDE + j];
            const float* vrow = &Vs[j * QK_STRIDE + c];
            #pragma unroll
            for (int u = 0; u < 32; u++)
                O[u] += p * vrow[4 * u];
        }
    }

    float inv = 1.0f / lrow;
    size_t ob = (size_t)qpos * QSIZE + h * HD + c;
    #pragma unroll
    for (int u = 0; u < 32; u++)
        g_attn[ob + 4 * u] = O[u] * inv;
}

// ---------------------------------------------------------------------------
extern "C" void kernel_launch(void* const* d_in, const int* in_sizes, int n_in,
                              void* d_out, int out_size)
{
    (void)in_sizes; (void)n_in; (void)out_size;
    const float* hidden    = (const float*)d_in[0];
    const int*   positions = (const int*)  d_in[1];
    const float* w_qkv     = (const float*)d_in[2];
    const float* b_qkv     = (const float*)d_in[3];
    const float* q_norm_w  = (const float*)d_in[4];
    const float* k_norm_w  = (const float*)d_in[5];
    const float* w_o       = (const float*)d_in[6];
    float*       out       = (float*)d_out;

    float *pqkv = nullptr, *pattn = nullptr;
    cudaGetSymbolAddress((void**)&pqkv,  g_qkv);
    cudaGetSymbolAddress((void**)&pattn, g_attn);

    // 1) QKV projection + bias
    {
        dim3 grid(QKV_OUT / 128, T_LEN / 128);
        sgemm_nt<true><<<grid, 256>>>(hidden, w_qkv, b_qkv, pqkv,
                                      T_LEN, QKV_OUT, HIDDEN);
    }

    // 2) RMSNorm + RoPE (in-place on g_qkv)
    norm_rope_kernel<<<T_LEN, 256>>>(positions, q_norm_w, k_norm_w);

    // 3) Causal attention
    {
        const int smem_bytes = (3 * AT_BM * QK_STRIDE + AT_BM * SS_STRIDE) * sizeof(float);
        cudaFuncSetAttribute(attn_kernel,
                             cudaFuncAttributeMaxDynamicSharedMemorySize, smem_bytes);
        dim3 grid(T_LEN / AT_BM, NH);
        attn_kernel<<<grid, 256, smem_bytes>>>();
    }

    // 4) Output projection
    {
        dim3 grid(HIDDEN / 128, T_LEN / 128);
        sgemm_nt<false><<<grid, 256>>>(pattn, w_o, nullptr, out,
                                       T_LEN, HIDDEN, QSIZE);
    }
}

// round 4
// speedup vs baseline: 1.6699x; 1.6699x over previous
#include <cuda_runtime.h>
#include <cuda_bf16.h>
#include <math.h>
#include <stdint.h>

#define T_LEN   2048
#define HIDDEN  4096
#define NH      32
#define HD      128
#define QSIZE   (NH*HD)          // 4096
#define QKV_OUT 12288
#define EPS     1e-5f
#define ROPE_THETA 1000000.0f

// ---------------------------------------------------------------------------
// Scratch (static device globals: allocation-free per harness rules)
// ---------------------------------------------------------------------------
__device__ float g_qkv [(size_t)T_LEN * QKV_OUT];   // QKV output, fp32
__device__ float g_attn[(size_t)T_LEN * QSIZE];     // attn output, fp32

__device__ __nv_bfloat16 g_h_hi  [(size_t)T_LEN  * HIDDEN];
__device__ __nv_bfloat16 g_h_lo  [(size_t)T_LEN  * HIDDEN];
__device__ __nv_bfloat16 g_wq_hi [(size_t)QKV_OUT * HIDDEN];
__device__ __nv_bfloat16 g_wq_lo [(size_t)QKV_OUT * HIDDEN];
__device__ __nv_bfloat16 g_wo_hi [(size_t)HIDDEN * QSIZE];
__device__ __nv_bfloat16 g_wo_lo [(size_t)HIDDEN * QSIZE];
__device__ __nv_bfloat16 g_at_hi [(size_t)T_LEN  * QSIZE];
__device__ __nv_bfloat16 g_at_lo [(size_t)T_LEN  * QSIZE];

// ---------------------------------------------------------------------------
// PTX helpers — ONLY arch-neutral (sm_80-era) instructions: ldmatrix,
// mma.sync, cp.async. (tcgen05/TMEM do NOT assemble: toolchain emits
// compute_103 PTX without the 'a' feature set.)
// ---------------------------------------------------------------------------
__device__ __forceinline__ uint32_t smem_u32(const void* p) {
    uint32_t a;
    asm("{ .reg .u64 t; cvta.to.shared.u64 t, %1; cvt.u32.u64 %0, t; }"
        : "=r"(a) : "l"(p));
    return a;
}

#define CP_ASYNC16(dst, src) \
    asm volatile("cp.async.cg.shared.global [%0], [%1], 16;" \
                 :: "r"(dst), "l"(src) : "memory")
#define CP_COMMIT() asm volatile("cp.async.commit_group;" ::: "memory")
template<int N>
__device__ __forceinline__ void cp_wait() {
    asm volatile("cp.async.wait_group %0;" :: "n"(N) : "memory");
}

#define LDSM_X4(R, addr) \
    asm volatile("ldmatrix.sync.aligned.m8n8.x4.shared.b16 {%0,%1,%2,%3}, [%4];" \
                 : "=r"((R)[0]), "=r"((R)[1]), "=r"((R)[2]), "=r"((R)[3]) \
                 : "r"(addr))

__device__ __forceinline__ void mma16816(float* c, const uint32_t* a,
                                         uint32_t b0, uint32_t b1) {
    asm volatile(
        "mma.sync.aligned.m16n8k16.row.col.f32.bf16.bf16.f32 "
        "{%0,%1,%2,%3}, {%4,%5,%6,%7}, {%8,%9}, {%0,%1,%2,%3};"
        : "+f"(c[0]), "+f"(c[1]), "+f"(c[2]), "+f"(c[3])
        : "r"(a[0]), "r"(a[1]), "r"(a[2]), "r"(a[3]), "r"(b0), "r"(b1));
}

// ---------------------------------------------------------------------------
// fp32 -> bf16 hi/lo split (x = hi + lo, ~16 mantissa bits total)
// ---------------------------------------------------------------------------
__global__ void split_kernel(const float* __restrict__ x,
                             __nv_bfloat16* __restrict__ hi,
                             __nv_bfloat16* __restrict__ lo, int n4)
{
    int i = blockIdx.x * blockDim.x + threadIdx.x;
    if (i >= n4) return;
    float4 v = ((const float4*)x)[i];
    __nv_bfloat16 h0 = __float2bfloat16(v.x);
    __nv_bfloat16 h1 = __float2bfloat16(v.y);
    __nv_bfloat16 h2 = __float2bfloat16(v.z);
    __nv_bfloat16 h3 = __float2bfloat16(v.w);
    __nv_bfloat16 l0 = __float2bfloat16(v.x - __bfloat162float(h0));
    __nv_bfloat16 l1 = __float2bfloat16(v.y - __bfloat162float(h1));
    __nv_bfloat16 l2 = __float2bfloat16(v.z - __bfloat162float(h2));
    __nv_bfloat16 l3 = __float2bfloat16(v.w - __bfloat162float(h3));
    __nv_bfloat162* ph = (__nv_bfloat162*)&hi[(size_t)i * 4];
    __nv_bfloat162* pl = (__nv_bfloat162*)&lo[(size_t)i * 4];
    ph[0] = __nv_bfloat162(h0, h1); ph[1] = __nv_bfloat162(h2, h3);
    pl[0] = __nv_bfloat162(l0, l1); pl[1] = __nv_bfloat162(l2, l3);
}

// ---------------------------------------------------------------------------
// HMMA bf16x3 GEMM: C[m][n] = sum_k A[m][k]*B[n][k] (+bias[n]), K = 4096.
// CTA 128x128, 8 warps (warp tile 32x64), KC=32 double-buffered via cp.async.
// smem rows padded to 40 bf16 (80 B) -> ldmatrix conflict-free.
// ---------------------------------------------------------------------------
#define GK   4096
#define KC   32
#define KSB  80                       // bytes per smem row (40 bf16)
#define TEN  (128 * KSB)              // 10240 B per tensor tile
#define STG  (4 * TEN)                // 40960 B per stage
#define GEMM_SMEM (2 * STG)           // 81920 B

__global__ __launch_bounds__(256, 1)
void gemm_hmma(const __nv_bfloat16* __restrict__ Ah,
               const __nv_bfloat16* __restrict__ Al,
               const __nv_bfloat16* __restrict__ Bh,
               const __nv_bfloat16* __restrict__ Bl,
               const float* __restrict__ bias, float* __restrict__ C, int N)
{
    extern __shared__ char smem[];
    const uint32_t sb = smem_u32(smem);
    const int tid  = threadIdx.x;
    const int wid  = tid >> 5;
    const int lane = tid & 31;
    const int wm = (wid & 3) * 32;        // warp row offset in CTA tile
    const int wn = (wid >> 2) * 64;       // warp col offset in CTA tile
    const int bm = blockIdx.x * 128;
    const int bn = blockIdx.y * 128;

    float acc[2][8][4];
    #pragma unroll
    for (int mi = 0; mi < 2; mi++)
        #pragma unroll
        for (int ni = 0; ni < 8; ni++)
            #pragma unroll
            for (int j = 0; j < 4; j++) acc[mi][ni][j] = 0.f;

    // per-thread load coords: f in {tid, tid+256}; r=f>>2 (row), s=f&3 (16B seg)
    const int r0 = tid >> 2,        s0 = tid & 3;
    const int r1 = (tid + 256) >> 2, s1 = tid & 3;  // (tid+256)&3 == tid&3

    auto issue_load = [&](int c, int buf) {
        const uint32_t base = sb + buf * STG;
        const int k0 = c * KC;
        {
            uint32_t doff = (uint32_t)(r0 * KSB + s0 * 16);
            size_t ga = (size_t)(bm + r0) * GK + k0 + s0 * 8;
            size_t gb = (size_t)(bn + r0) * GK + k0 + s0 * 8;
            CP_ASYNC16(base +           doff, Ah + ga);
            CP_ASYNC16(base +     TEN + doff, Al + ga);
            CP_ASYNC16(base + 2 * TEN + doff, Bh + gb);
            CP_ASYNC16(base + 3 * TEN + doff, Bl + gb);
        }
        {
            uint32_t doff = (uint32_t)(r1 * KSB + s1 * 16);
            size_t ga = (size_t)(bm + r1) * GK + k0 + s1 * 8;
            size_t gb = (size_t)(bn + r1) * GK + k0 + s1 * 8;
            CP_ASYNC16(base +           doff, Ah + ga);
            CP_ASYNC16(base +     TEN + doff, Al + ga);
            CP_ASYNC16(base + 2 * TEN + doff, Bh + gb);
            CP_ASYNC16(base + 3 * TEN + doff, Bl + gb);
        }
        CP_COMMIT();
    };

    const int NCHUNK = GK / KC;          // 128
    issue_load(0, 0);

    // ldmatrix lane addressing: row = lane&15, 16B col-group = lane>>4
    const uint32_t lrow = (uint32_t)(lane & 15) * KSB;
    const uint32_t lcol = (uint32_t)(lane >> 4) * 16;

    for (int c = 0; c < NCHUNK; c++) {
        const int buf = c & 1;
        if (c + 1 < NCHUNK) issue_load(c + 1, buf ^ 1);
        if (c + 1 < NCHUNK) cp_wait<1>(); else cp_wait<0>();
        __syncthreads();

        const uint32_t base = sb + buf * STG;
        const uint32_t aA = base +           (uint32_t)wm * KSB + lrow + lcol;
        const uint32_t aB = base + 2 * TEN + (uint32_t)wn * KSB + lrow + lcol;

        #pragma unroll
        for (int ks = 0; ks < 2; ks++) {
            const uint32_t kof = ks * 32;
            uint32_t ah[2][4], al[2][4];
            #pragma unroll
            for (int mi = 0; mi < 2; mi++) {
                LDSM_X4(ah[mi], aA + mi * 16 * KSB + kof);
                LDSM_X4(al[mi], aA + TEN + mi * 16 * KSB + kof);
            }
            #pragma unroll
            for (int half = 0; half < 2; half++) {
                uint32_t bh[2][4], bl[2][4];
                #pragma unroll
                for (int p = 0; p < 2; p++) {
                    const uint32_t boff = (half * 2 + p) * 16 * KSB + kof;
                    LDSM_X4(bh[p], aB + boff);
                    LDSM_X4(bl[p], aB + TEN + boff);
                }
                #pragma unroll
                for (int mi = 0; mi < 2; mi++)
                    #pragma unroll
                    for (int p = 0; p < 2; p++)
                        #pragma unroll
                        for (int sub = 0; sub < 2; sub++) {
                            const int ni = half * 4 + p * 2 + sub;
                            mma16816(acc[mi][ni], ah[mi], bh[p][sub], bh[p][sub + 2]);
                            mma16816(acc[mi][ni], ah[mi], bl[p][sub], bl[p][sub + 2]);
                            mma16816(acc[mi][ni], al[mi], bh[p][sub], bh[p][sub + 2]);
                        }
            }
        }
        __syncthreads();
    }

    // Epilogue: acc layout m16n8: c0/c1 row=lane>>2 col=(lane&3)*2(+1); c2/c3 row+8
    const int er = lane >> 2;
    const int ec = (lane & 3) * 2;
    #pragma unroll
    for (int mi = 0; mi < 2; mi++) {
        #pragma unroll
        for (int ni = 0; ni < 8; ni++) {
            int row = bm + wm + mi * 16 + er;
            int col = bn + wn + ni * 8 + ec;
            float b0 = bias ? bias[col] : 0.f;
            float b1 = bias ? bias[col + 1] : 0.f;
            float2 v0 = make_float2(acc[mi][ni][0] + b0, acc[mi][ni][1] + b1);
            float2 v1 = make_float2(acc[mi][ni][2] + b0, acc[mi][ni][3] + b1);
            *(float2*)&C[(size_t)row * N + col]       = v0;
            *(float2*)&C[(size_t)(row + 8) * N + col] = v1;
        }
    }
}

// ---------------------------------------------------------------------------
// Per-token RMSNorm (full 4096-dim q and k) + RoPE, in place on g_qkv.
// ---------------------------------------------------------------------------
__global__ void norm_rope_kernel(const int* __restrict__ positions,
                                 const float* __restrict__ qw,
                                 const float* __restrict__ kw)
{
    const int t   = blockIdx.x;
    const int tid = threadIdx.x;
    float* row = g_qkv + (size_t)t * QKV_OUT;

    __shared__ float red[256];
    __shared__ float s_scale_q, s_scale_k;

    float sq = 0.f, sk = 0.f;
    for (int i = tid; i < QSIZE; i += 256) {
        float x = row[i];         sq += x * x;
        float y = row[QSIZE + i]; sk += y * y;
    }

    red[tid] = sq; __syncthreads();
    for (int s = 128; s > 0; s >>= 1) {
        if (tid < s) red[tid] += red[tid + s];
        __syncthreads();
    }
    if (tid == 0) s_scale_q = rsqrtf(red[0] * (1.0f / QSIZE) + EPS);
    __syncthreads();

    red[tid] = sk; __syncthreads();
    for (int s = 128; s > 0; s >>= 1) {
        if (tid < s) red[tid] += red[tid + s];
        __syncthreads();
    }
    if (tid == 0) s_scale_k = rsqrtf(red[0] * (1.0f / QSIZE) + EPS);
    __syncthreads();

    const float scq = s_scale_q, sck = s_scale_k;
    const float pos = (float)positions[t];

    for (int idx = tid; idx < NH * 64; idx += 256) {
        int h = idx >> 6;
        int d = idx & 63;
        float inv_freq = powf(ROPE_THETA, -(float)d * (1.0f / 64.0f));
        float ang = pos * inv_freq;
        float sn, cs;
        sincosf(ang, &sn, &cs);

        int off = h * HD;
        {
            float x1 = row[off + d]      * scq * qw[off + d];
            float x2 = row[off + 64 + d] * scq * qw[off + 64 + d];
            row[off + d]      = x1 * cs - x2 * sn;
            row[off + 64 + d] = x2 * cs + x1 * sn;
        }
        {
            int offk = QSIZE + off;
            float x1 = row[offk + d]      * sck * kw[off + d];
            float x2 = row[offk + 64 + d] * sck * kw[off + 64 + d];
            row[offk + d]      = x1 * cs - x2 * sn;
            row[offk + 64 + d] = x2 * cs + x1 * sn;
        }
    }
}

// ---------------------------------------------------------------------------
// Flash-style causal attention, fp32 (known-good from round 2).
// ---------------------------------------------------------------------------
#define AT_BM 64
#define AT_BN 64
#define QK_STRIDE 132
#define SS_STRIDE 68

__global__ __launch_bounds__(256, 1)
void attn_kernel()
{
    extern __shared__ float asmem[];
    float* Qs = asmem;
    float* Ks = Qs + AT_BM * QK_STRIDE;
    float* Vs = Ks + AT_BN * QK_STRIDE;
    float* Ss = Vs + AT_BN * QK_STRIDE;

    const int qb  = blockIdx.x;
    const int h   = blockIdx.y;
    const int tid = threadIdx.x;
    const int r   = tid >> 2;
    const int c   = tid & 3;
    const float scale = 0.08838834764831845f;

    for (int f = tid; f < AT_BM * 32; f += 256) {
        int m  = f >> 5;
        int dq = (f & 31) << 2;
        *(float4*)&Qs[m * QK_STRIDE + dq] =
            *(const float4*)&g_qkv[(size_t)(qb * AT_BM + m) * QKV_OUT + h * HD + dq];
    }

    float O[32];
    #pragma unroll
    for (int u = 0; u < 32; u++) O[u] = 0.f;
    float mrow = -1e30f, lrow = 0.f;

    const int qpos = qb * AT_BM + r;
    const int ntiles = qb + 1;

    for (int kb = 0; kb < ntiles; kb++) {
        __syncthreads();
        for (int f = tid; f < AT_BN * 32; f += 256) {
            int m  = f >> 5;
            int dq = (f & 31) << 2;
            size_t gb = (size_t)(kb * AT_BN + m) * QKV_OUT + h * HD + dq;
            *(float4*)&Ks[m * QK_STRIDE + dq] = *(const float4*)&g_qkv[gb + QSIZE];
            *(float4*)&Vs[m * QK_STRIDE + dq] = *(const float4*)&g_qkv[gb + 2 * QSIZE];
        }
        __syncthreads();

        float s[16];
        #pragma unroll
        for (int jj = 0; jj < 16; jj++) s[jj] = 0.f;

        for (int d = 0; d < HD; d += 4) {
            float4 qv = *(float4*)&Qs[r * QK_STRIDE + d];
            #pragma unroll
            for (int jj = 0; jj < 16; jj++) {
                int j = c + 4 * jj;
                float4 kv = *(float4*)&Ks[j * QK_STRIDE + d];
                s[jj] += qv.x * kv.x + qv.y * kv.y + qv.z * kv.z + qv.w * kv.w;
            }
        }

        float tmax = -1e30f;
        #pragma unroll
        for (int jj = 0; jj < 16; jj++) {
            int kpos = kb * AT_BN + c + 4 * jj;
            s[jj] = (kpos <= qpos) ? s[jj] * scale : -1e30f;
            tmax = fmaxf(tmax, s[jj]);
        }
        tmax = fmaxf(tmax, __shfl_xor_sync(0xffffffffu, tmax, 1));
        tmax = fmaxf(tmax, __shfl_xor_sync(0xffffffffu, tmax, 2));

        float mnew = fmaxf(mrow, tmax);
        float psum = 0.f;
        #pragma unroll
        for (int jj = 0; jj < 16; jj++) {
            float p = __expf(s[jj] - mnew);
            Ss[r * SS_STRIDE + c + 4 * jj] = p;
            psum += p;
        }
        psum += __shfl_xor_sync(0xffffffffu, psum, 1);
        psum += __shfl_xor_sync(0xffffffffu, psum, 2);

        float alpha = __expf(mrow - mnew);
        lrow = lrow * alpha + psum;
        mrow = mnew;
        #pragma unroll
        for (int u = 0; u < 32; u++) O[u] *= alpha;

        __syncthreads();

        for (int j = 0; j < AT_BN; j++) {
            float p = Ss[r * SS_STRIDE + j];
            const float* vrow = &Vs[j * QK_STRIDE + c];
            #pragma unroll
            for (int u = 0; u < 32; u++)
                O[u] += p * vrow[4 * u];
        }
    }

    float inv = 1.0f / lrow;
    size_t ob = (size_t)qpos * QSIZE + h * HD + c;
    #pragma unroll
    for (int u = 0; u < 32; u++)
        g_attn[ob + 4 * u] = O[u] * inv;
}

// ---------------------------------------------------------------------------
extern "C" void kernel_launch(void* const* d_in, const int* in_sizes, int n_in,
                              void* d_out, int out_size)
{
    (void)in_sizes; (void)n_in; (void)out_size;
    const float* hidden    = (const float*)d_in[0];
    const int*   positions = (const int*)  d_in[1];
    const float* w_qkv     = (const float*)d_in[2];
    const float* b_qkv     = (const float*)d_in[3];
    const float* q_norm_w  = (const float*)d_in[4];
    const float* k_norm_w  = (const float*)d_in[5];
    const float* w_o       = (const float*)d_in[6];
    float*       out       = (float*)d_out;

    float *pqkv = nullptr, *pattn = nullptr;
    __nv_bfloat16 *hh, *hl, *wqh, *wql, *woh, *wol, *ath, *atl;
    cudaGetSymbolAddress((void**)&pqkv,  g_qkv);
    cudaGetSymbolAddress((void**)&pattn, g_attn);
    cudaGetSymbolAddress((void**)&hh,  g_h_hi);
    cudaGetSymbolAddress((void**)&hl,  g_h_lo);
    cudaGetSymbolAddress((void**)&wqh, g_wq_hi);
    cudaGetSymbolAddress((void**)&wql, g_wq_lo);
    cudaGetSymbolAddress((void**)&woh, g_wo_hi);
    cudaGetSymbolAddress((void**)&wol, g_wo_lo);
    cudaGetSymbolAddress((void**)&ath, g_at_hi);
    cudaGetSymbolAddress((void**)&atl, g_at_lo);

    static bool attr_set = false;
    if (!attr_set) {
        cudaFuncSetAttribute(gemm_hmma, cudaFuncAttributeMaxDynamicSharedMemorySize,
                             GEMM_SMEM);
        cudaFuncSetAttribute(attn_kernel, cudaFuncAttributeMaxDynamicSharedMemorySize,
                             (3 * AT_BM * QK_STRIDE + AT_BM * SS_STRIDE) * (int)sizeof(float));
        attr_set = true;
    }

    // 0) split inputs to bf16 hi/lo
    {
        int n4;
        n4 = (T_LEN * HIDDEN) / 4;
        split_kernel<<<(n4 + 255) / 256, 256>>>(hidden, hh, hl, n4);
        n4 = (QKV_OUT * HIDDEN) / 4;
        split_kernel<<<(n4 + 255) / 256, 256>>>(w_qkv, wqh, wql, n4);
        n4 = (HIDDEN * QSIZE) / 4;
        split_kernel<<<(n4 + 255) / 256, 256>>>(w_o, woh, wol, n4);
    }

    // 1) QKV projection + bias (HMMA bf16x3)
    {
        dim3 grid(T_LEN / 128, QKV_OUT / 128);
        gemm_hmma<<<grid, 256, GEMM_SMEM>>>(hh, hl, wqh, wql, b_qkv, pqkv, QKV_OUT);
    }

    // 2) RMSNorm + RoPE
    norm_rope_kernel<<<T_LEN, 256>>>(positions, q_norm_w, k_norm_w);

    // 3) Causal attention
    {
        const int smem_bytes = (3 * AT_BM * QK_STRIDE + AT_BM * SS_STRIDE) * sizeof(float);
        dim3 grid(T_LEN / AT_BM, NH);
        attn_kernel<<<grid, 256, smem_bytes>>>();
    }

    // 4) split attn output, then output projection (HMMA bf16x3)
    {
        int n4 = (T_LEN * QSIZE) / 4;
        split_kernel<<<(n4 + 255) / 256, 256>>>(pattn, ath, atl, n4);
        dim3 grid(T_LEN / 128, HIDDEN / 128);
        gemm_hmma<<<grid, 256, GEMM_SMEM>>>(ath, atl, woh, wol, nullptr, out, HIDDEN);
    }
}

// round 5
// speedup vs baseline: 1.6965x; 1.0160x over previous
#include <cuda_runtime.h>
#include <cuda_bf16.h>
#include <math.h>
#include <stdint.h>

#define T_LEN   2048
#define HIDDEN  4096
#define NH      32
#define HD      128
#define QSIZE   (NH*HD)          // 4096
#define QKV_OUT 12288
#define EPS     1e-5f
#define ROPE_THETA 1000000.0f

// ---------------------------------------------------------------------------
// Scratch (static device globals: allocation-free per harness rules)
// ---------------------------------------------------------------------------
__device__ float g_qkv [(size_t)T_LEN * QKV_OUT];   // QKV output, fp32
__device__ float g_attn[(size_t)T_LEN * QSIZE];     // attn output, fp32

__device__ __nv_bfloat16 g_h_hi  [(size_t)T_LEN  * HIDDEN];
__device__ __nv_bfloat16 g_h_lo  [(size_t)T_LEN  * HIDDEN];
__device__ __nv_bfloat16 g_wq_hi [(size_t)QKV_OUT * HIDDEN];
__device__ __nv_bfloat16 g_wq_lo [(size_t)QKV_OUT * HIDDEN];
__device__ __nv_bfloat16 g_wo_hi [(size_t)HIDDEN * QSIZE];
__device__ __nv_bfloat16 g_wo_lo [(size_t)HIDDEN * QSIZE];
__device__ __nv_bfloat16 g_at_hi [(size_t)T_LEN  * QSIZE];
__device__ __nv_bfloat16 g_at_lo [(size_t)T_LEN  * QSIZE];

// ---------------------------------------------------------------------------
// PTX helpers — arch-neutral (sm_80-era) only: ldmatrix, mma.sync, cp.async.
// ---------------------------------------------------------------------------
__device__ __forceinline__ uint32_t smem_u32(const void* p) {
    uint32_t a;
    asm("{ .reg .u64 t; cvta.to.shared.u64 t, %1; cvt.u32.u64 %0, t; }"
        : "=r"(a) : "l"(p));
    return a;
}

#define CP_ASYNC16(dst, src) \
    asm volatile("cp.async.cg.shared.global [%0], [%1], 16;" \
                 :: "r"(dst), "l"(src) : "memory")
#define CP_COMMIT() asm volatile("cp.async.commit_group;" ::: "memory")
template<int N>
__device__ __forceinline__ void cp_wait() {
    asm volatile("cp.async.wait_group %0;" :: "n"(N) : "memory");
}

#define LDSM_X4(R, addr) \
    asm volatile("ldmatrix.sync.aligned.m8n8.x4.shared.b16 {%0,%1,%2,%3}, [%4];" \
                 : "=r"((R)[0]), "=r"((R)[1]), "=r"((R)[2]), "=r"((R)[3]) \
                 : "r"(addr))

__device__ __forceinline__ void mma16816(float* c, const uint32_t* a,
                                         uint32_t b0, uint32_t b1) {
    asm volatile(
        "mma.sync.aligned.m16n8k16.row.col.f32.bf16.bf16.f32 "
        "{%0,%1,%2,%3}, {%4,%5,%6,%7}, {%8,%9}, {%0,%1,%2,%3};"
        : "+f"(c[0]), "+f"(c[1]), "+f"(c[2]), "+f"(c[3])
        : "r"(a[0]), "r"(a[1]), "r"(a[2]), "r"(a[3]), "r"(b0), "r"(b1));
}

// ---------------------------------------------------------------------------
// fp32 -> bf16 hi/lo split (x = hi + lo, ~16 mantissa bits total)
// ---------------------------------------------------------------------------
__global__ void split_kernel(const float* __restrict__ x,
                             __nv_bfloat16* __restrict__ hi,
                             __nv_bfloat16* __restrict__ lo, int n4)
{
    int i = blockIdx.x * blockDim.x + threadIdx.x;
    if (i >= n4) return;
    float4 v = ((const float4*)x)[i];
    __nv_bfloat16 h0 = __float2bfloat16(v.x);
    __nv_bfloat16 h1 = __float2bfloat16(v.y);
    __nv_bfloat16 h2 = __float2bfloat16(v.z);
    __nv_bfloat16 h3 = __float2bfloat16(v.w);
    __nv_bfloat16 l0 = __float2bfloat16(v.x - __bfloat162float(h0));
    __nv_bfloat16 l1 = __float2bfloat16(v.y - __bfloat162float(h1));
    __nv_bfloat16 l2 = __float2bfloat16(v.z - __bfloat162float(h2));
    __nv_bfloat16 l3 = __float2bfloat16(v.w - __bfloat162float(h3));
    __nv_bfloat162* ph = (__nv_bfloat162*)&hi[(size_t)i * 4];
    __nv_bfloat162* pl = (__nv_bfloat162*)&lo[(size_t)i * 4];
    ph[0] = __nv_bfloat162(h0, h1); ph[1] = __nv_bfloat162(h2, h3);
    pl[0] = __nv_bfloat162(l0, l1); pl[1] = __nv_bfloat162(l2, l3);
}

// ---------------------------------------------------------------------------
// HMMA bf16x3 GEMM: C[m][n] = sum_k A[m][k]*B[n][k] (+bias[n]), K = 4096.
// CTA 128x128, 8 warps (warp tile 32x64). 4-stage cp.async pipeline,
// ONE __syncthreads per chunk, term-major MMA order (no same-acc RAW chain).
// smem rows padded to 40 bf16 (80 B) -> ldmatrix conflict-free.
// ---------------------------------------------------------------------------
#define GK     4096
#define KC     32
#define NSTAGE 4
#define KSB    80                     // bytes per smem row (40 bf16)
#define TEN    (128 * KSB)            // 10240 B per tensor tile
#define STG    (4 * TEN)              // 40960 B per stage
#define GEMM_SMEM (NSTAGE * STG)      // 163840 B

__global__ __launch_bounds__(256, 1)
void gemm_hmma(const __nv_bfloat16* __restrict__ Ah,
               const __nv_bfloat16* __restrict__ Al,
               const __nv_bfloat16* __restrict__ Bh,
               const __nv_bfloat16* __restrict__ Bl,
               const float* __restrict__ bias, float* __restrict__ C, int N)
{
    extern __shared__ char smem[];
    const uint32_t sb = smem_u32(smem);
    const int tid  = threadIdx.x;
    const int wid  = tid >> 5;
    const int lane = tid & 31;
    const int wm = (wid & 3) * 32;        // warp row offset in CTA tile
    const int wn = (wid >> 2) * 64;       // warp col offset in CTA tile
    const int bm = blockIdx.x * 128;
    const int bn = blockIdx.y * 128;

    float acc[2][8][4];
    #pragma unroll
    for (int mi = 0; mi < 2; mi++)
        #pragma unroll
        for (int ni = 0; ni < 8; ni++)
            #pragma unroll
            for (int j = 0; j < 4; j++) acc[mi][ni][j] = 0.f;

    // per-thread load coords: f in {tid, tid+256}; r=f>>2 (row), s=f&3 (16B seg)
    const int r0 = tid >> 2,         s0 = tid & 3;
    const int r1 = (tid + 256) >> 2;

    auto issue_load = [&](int c, int buf) {
        const uint32_t base = sb + buf * STG;
        const int k0 = c * KC;
        {
            uint32_t doff = (uint32_t)(r0 * KSB + s0 * 16);
            size_t ga = (size_t)(bm + r0) * GK + k0 + s0 * 8;
            size_t gb = (size_t)(bn + r0) * GK + k0 + s0 * 8;
            CP_ASYNC16(base +           doff, Ah + ga);
            CP_ASYNC16(base +     TEN + doff, Al + ga);
            CP_ASYNC16(base + 2 * TEN + doff, Bh + gb);
            CP_ASYNC16(base + 3 * TEN + doff, Bl + gb);
        }
        {
            uint32_t doff = (uint32_t)(r1 * KSB + s0 * 16);
            size_t ga = (size_t)(bm + r1) * GK + k0 + s0 * 8;
            size_t gb = (size_t)(bn + r1) * GK + k0 + s0 * 8;
            CP_ASYNC16(base +           doff, Ah + ga);
            CP_ASYNC16(base +     TEN + doff, Al + ga);
            CP_ASYNC16(base + 2 * TEN + doff, Bh + gb);
            CP_ASYNC16(base + 3 * TEN + doff, Bl + gb);
        }
    };

    const int NCHUNK = GK / KC;          // 128

    // Prologue: stages 0..NSTAGE-2 in flight
    #pragma unroll
    for (int s = 0; s < NSTAGE - 1; s++) {
        issue_load(s, s);
        CP_COMMIT();
    }

    // ldmatrix lane addressing: row = lane&15, 16B col-group = lane>>4
    const uint32_t lrow = (uint32_t)(lane & 15) * KSB;
    const uint32_t lcol = (uint32_t)(lane >> 4) * 16;

    for (int c = 0; c < NCHUNK; c++) {
        // chunk c guaranteed resident after this wait
        cp_wait<NSTAGE - 2>();
        __syncthreads();   // all warps done reading slot (c-1)%NSTAGE; data of c visible

        // refill the slot that barrier just retired
        if (c + NSTAGE - 1 < NCHUNK)
            issue_load(c + NSTAGE - 1, (c + NSTAGE - 1) % NSTAGE);
        CP_COMMIT();       // (possibly empty group: keeps wait_group indexing)

        const uint32_t base = sb + (c % NSTAGE) * STG;
        const uint32_t aA = base +           (uint32_t)wm * KSB + lrow + lcol;
        const uint32_t aB = base + 2 * TEN + (uint32_t)wn * KSB + lrow + lcol;

        #pragma unroll
        for (int ks = 0; ks < 2; ks++) {
            const uint32_t kof = ks * 32;
            uint32_t ah[2][4], al[2][4];
            #pragma unroll
            for (int mi = 0; mi < 2; mi++) {
                LDSM_X4(ah[mi], aA + mi * 16 * KSB + kof);
                LDSM_X4(al[mi], aA + TEN + mi * 16 * KSB + kof);
            }
            #pragma unroll
            for (int half = 0; half < 2; half++) {
                uint32_t bh[2][4], bl[2][4];
                #pragma unroll
                for (int p = 0; p < 2; p++) {
                    const uint32_t boff = (half * 2 + p) * 16 * KSB + kof;
                    LDSM_X4(bh[p], aB + boff);
                    LDSM_X4(bl[p], aB + TEN + boff);
                }
                // Term-major: 8 distinct accumulators between same-acc reuse
                #pragma unroll
                for (int mi = 0; mi < 2; mi++)
                    #pragma unroll
                    for (int p = 0; p < 2; p++)
                        #pragma unroll
                        for (int sub = 0; sub < 2; sub++)
                            mma16816(acc[mi][half * 4 + p * 2 + sub],
                                     ah[mi], bh[p][sub], bh[p][sub + 2]);
                #pragma unroll
                for (int mi = 0; mi < 2; mi++)
                    #pragma unroll
                    for (int p = 0; p < 2; p++)
                        #pragma unroll
                        for (int sub = 0; sub < 2; sub++)
                            mma16816(acc[mi][half * 4 + p * 2 + sub],
                                     ah[mi], bl[p][sub], bl[p][sub + 2]);
                #pragma unroll
                for (int mi = 0; mi < 2; mi++)
                    #pragma unroll
                    for (int p = 0; p < 2; p++)
                        #pragma unroll
                        for (int sub = 0; sub < 2; sub++)
                            mma16816(acc[mi][half * 4 + p * 2 + sub],
                                     al[mi], bh[p][sub], bh[p][sub + 2]);
            }
        }
    }

    // Epilogue: m16n8 acc layout: c0/c1 row=lane>>2 col=(lane&3)*2; c2/c3 row+8
    const int er = lane >> 2;
    const int ec = (lane & 3) * 2;
    #pragma unroll
    for (int mi = 0; mi < 2; mi++) {
        #pragma unroll
        for (int ni = 0; ni < 8; ni++) {
            int row = bm + wm + mi * 16 + er;
            int col = bn + wn + ni * 8 + ec;
            float b0 = bias ? bias[col] : 0.f;
            float b1 = bias ? bias[col + 1] : 0.f;
            float2 v0 = make_float2(acc[mi][ni][0] + b0, acc[mi][ni][1] + b1);
            float2 v1 = make_float2(acc[mi][ni][2] + b0, acc[mi][ni][3] + b1);
            *(float2*)&C[(size_t)row * N + col]       = v0;
            *(float2*)&C[(size_t)(row + 8) * N + col] = v1;
        }
    }
}

// ---------------------------------------------------------------------------
// Per-token RMSNorm (full 4096-dim q and k) + RoPE, in place on g_qkv.
// ---------------------------------------------------------------------------
__global__ void norm_rope_kernel(const int* __restrict__ positions,
                                 const float* __restrict__ qw,
                                 const float* __restrict__ kw)
{
    const int t   = blockIdx.x;
    const int tid = threadIdx.x;
    float* row = g_qkv + (size_t)t * QKV_OUT;

    __shared__ float red[256];
    __shared__ float s_scale_q, s_scale_k;

    float sq = 0.f, sk = 0.f;
    for (int i = tid; i < QSIZE; i += 256) {
        float x = row[i];         sq += x * x;
        float y = row[QSIZE + i]; sk += y * y;
    }

    red[tid] = sq; __syncthreads();
    for (int s = 128; s > 0; s >>= 1) {
        if (tid < s) red[tid] += red[tid + s];
        __syncthreads();
    }
    if (tid == 0) s_scale_q = rsqrtf(red[0] * (1.0f / QSIZE) + EPS);
    __syncthreads();

    red[tid] = sk; __syncthreads();
    for (int s = 128; s > 0; s >>= 1) {
        if (tid < s) red[tid] += red[tid + s];
        __syncthreads();
    }
    if (tid == 0) s_scale_k = rsqrtf(red[0] * (1.0f / QSIZE) + EPS);
    __syncthreads();

    const float scq = s_scale_q, sck = s_scale_k;
    const float pos = (float)positions[t];

    for (int idx = tid; idx < NH * 64; idx += 256) {
        int h = idx >> 6;
        int d = idx & 63;
        float inv_freq = powf(ROPE_THETA, -(float)d * (1.0f / 64.0f));
        float ang = pos * inv_freq;
        float sn, cs;
        sincosf(ang, &sn, &cs);

        int off = h * HD;
        {
            float x1 = row[off + d]      * scq * qw[off + d];
            float x2 = row[off + 64 + d] * scq * qw[off + 64 + d];
            row[off + d]      = x1 * cs - x2 * sn;
            row[off + 64 + d] = x2 * cs + x1 * sn;
        }
        {
            int offk = QSIZE + off;
            float x1 = row[offk + d]      * sck * kw[off + d];
            float x2 = row[offk + 64 + d] * sck * kw[off + 64 + d];
            row[offk + d]      = x1 * cs - x2 * sn;
            row[offk + 64 + d] = x2 * cs + x1 * sn;
        }
    }
}

// ---------------------------------------------------------------------------
// Flash-style causal attention, fp32 (known-good).
// ---------------------------------------------------------------------------
#define AT_BM 64
#define AT_BN 64
#define QK_STRIDE 132
#define SS_STRIDE 68

__global__ __launch_bounds__(256, 1)
void attn_kernel()
{
    extern __shared__ float asmem[];
    float* Qs = asmem;
    float* Ks = Qs + AT_BM * QK_STRIDE;
    float* Vs = Ks + AT_BN * QK_STRIDE;
    float* Ss = Vs + AT_BN * QK_STRIDE;

    const int qb  = blockIdx.x;
    const int h   = blockIdx.y;
    const int tid = threadIdx.x;
    const int r   = tid >> 2;
    const int c   = tid & 3;
    const float scale = 0.08838834764831845f;

    for (int f = tid; f < AT_BM * 32; f += 256) {
        int m  = f >> 5;
        int dq = (f & 31) << 2;
        *(float4*)&Qs[m * QK_STRIDE + dq] =
            *(const float4*)&g_qkv[(size_t)(qb * AT_BM + m) * QKV_OUT + h * HD + dq];
    }

    float O[32];
    #pragma unroll
    for (int u = 0; u < 32; u++) O[u] = 0.f;
    float mrow = -1e30f, lrow = 0.f;

    const int qpos = qb * AT_BM + r;
    const int ntiles = qb + 1;

    for (int kb = 0; kb < ntiles; kb++) {
        __syncthreads();
        for (int f = tid; f < AT_BN * 32; f += 256) {
            int m  = f >> 5;
            int dq = (f & 31) << 2;
            size_t gb = (size_t)(kb * AT_BN + m) * QKV_OUT + h * HD + dq;
            *(float4*)&Ks[m * QK_STRIDE + dq] = *(const float4*)&g_qkv[gb + QSIZE];
            *(float4*)&Vs[m * QK_STRIDE + dq] = *(const float4*)&g_qkv[gb + 2 * QSIZE];
        }
        __syncthreads();

        float s[16];
        #pragma unroll
        for (int jj = 0; jj < 16; jj++) s[jj] = 0.f;

        for (int d = 0; d < HD; d += 4) {
            float4 qv = *(float4*)&Qs[r * QK_STRIDE + d];
            #pragma unroll
            for (int jj = 0; jj < 16; jj++) {
                int j = c + 4 * jj;
                float4 kv = *(float4*)&Ks[j * QK_STRIDE + d];
                s[jj] += qv.x * kv.x + qv.y * kv.y + qv.z * kv.z + qv.w * kv.w;
            }
        }

        float tmax = -1e30f;
        #pragma unroll
        for (int jj = 0; jj < 16; jj++) {
            int kpos = kb * AT_BN + c + 4 * jj;
            s[jj] = (kpos <= qpos) ? s[jj] * scale : -1e30f;
            tmax = fmaxf(tmax, s[jj]);
        }
        tmax = fmaxf(tmax, __shfl_xor_sync(0xffffffffu, tmax, 1));
        tmax = fmaxf(tmax, __shfl_xor_sync(0xffffffffu, tmax, 2));

        float mnew = fmaxf(mrow, tmax);
        float psum = 0.f;
        #pragma unroll
        for (int jj = 0; jj < 16; jj++) {
            float p = __expf(s[jj] - mnew);
            Ss[r * SS_STRIDE + c + 4 * jj] = p;
            psum += p;
        }
        psum += __shfl_xor_sync(0xffffffffu, psum, 1);
        psum += __shfl_xor_sync(0xffffffffu, psum, 2);

        float alpha = __expf(mrow - mnew);
        lrow = lrow * alpha + psum;
        mrow = mnew;
        #pragma unroll
        for (int u = 0; u < 32; u++) O[u] *= alpha;

        __syncthreads();

        for (int j = 0; j < AT_BN; j++) {
            float p = Ss[r * SS_STRIDE + j];
            const float* vrow = &Vs[j * QK_STRIDE + c];
            #pragma unroll
            for (int u = 0; u < 32; u++)
                O[u] += p * vrow[4 * u];
        }
    }

    float inv = 1.0f / lrow;
    size_t ob = (size_t)qpos * QSIZE + h * HD + c;
    #pragma unroll
    for (int u = 0; u < 32; u++)
        g_attn[ob + 4 * u] = O[u] * inv;
}

// ---------------------------------------------------------------------------
extern "C" void kernel_launch(void* const* d_in, const int* in_sizes, int n_in,
                              void* d_out, int out_size)
{
    (void)in_sizes; (void)n_in; (void)out_size;
    const float* hidden    = (const float*)d_in[0];
    const int*   positions = (const int*)  d_in[1];
    const float* w_qkv     = (const float*)d_in[2];
    const float* b_qkv     = (const float*)d_in[3];
    const float* q_norm_w  = (const float*)d_in[4];
    const float* k_norm_w  = (const float*)d_in[5];
    const float* w_o       = (const float*)d_in[6];
    float*       out       = (float*)d_out;

    float *pqkv = nullptr, *pattn = nullptr;
    __nv_bfloat16 *hh, *hl, *wqh, *wql, *woh, *wol, *ath, *atl;
    cudaGetSymbolAddress((void**)&pqkv,  g_qkv);
    cudaGetSymbolAddress((void**)&pattn, g_attn);
    cudaGetSymbolAddress((void**)&hh,  g_h_hi);
    cudaGetSymbolAddress((void**)&hl,  g_h_lo);
    cudaGetSymbolAddress((void**)&wqh, g_wq_hi);
    cudaGetSymbolAddress((void**)&wql, g_wq_lo);
    cudaGetSymbolAddress((void**)&woh, g_wo_hi);
    cudaGetSymbolAddress((void**)&wol, g_wo_lo);
    cudaGetSymbolAddress((void**)&ath, g_at_hi);
    cudaGetSymbolAddress((void**)&atl, g_at_lo);

    static bool attr_set = false;
    if (!attr_set) {
        cudaFuncSetAttribute(gemm_hmma, cudaFuncAttributeMaxDynamicSharedMemorySize,
                             GEMM_SMEM);
        cudaFuncSetAttribute(attn_kernel, cudaFuncAttributeMaxDynamicSharedMemorySize,
                             (3 * AT_BM * QK_STRIDE + AT_BM * SS_STRIDE) * (int)sizeof(float));
        attr_set = true;
    }

    // 0) split inputs to bf16 hi/lo
    {
        int n4;
        n4 = (T_LEN * HIDDEN) / 4;
        split_kernel<<<(n4 + 255) / 256, 256>>>(hidden, hh, hl, n4);
        n4 = (QKV_OUT * HIDDEN) / 4;
        split_kernel<<<(n4 + 255) / 256, 256>>>(w_qkv, wqh, wql, n4);
        n4 = (HIDDEN * QSIZE) / 4;
        split_kernel<<<(n4 + 255) / 256, 256>>>(w_o, woh, wol, n4);
    }

    // 1) QKV projection + bias (HMMA bf16x3)
    {
        dim3 grid(T_LEN / 128, QKV_OUT / 128);
        gemm_hmma<<<grid, 256, GEMM_SMEM>>>(hh, hl, wqh, wql, b_qkv, pqkv, QKV_OUT);
    }

    // 2) RMSNorm + RoPE
    norm_rope_kernel<<<T_LEN, 256>>>(positions, q_norm_w, k_norm_w);

    // 3) Causal attention
    {
        const int smem_bytes = (3 * AT_BM * QK_STRIDE + AT_BM * SS_STRIDE) * sizeof(float);
        dim3 grid(T_LEN / AT_BM, NH);
        attn_kernel<<<grid, 256, smem_bytes>>>();
    }

    // 4) split attn output, then output projection (HMMA bf16x3)
    {
        int n4 = (T_LEN * QSIZE) / 4;
        split_kernel<<<(n4 + 255) / 256, 256>>>(pattn, ath, atl, n4);
        dim3 grid(T_LEN / 128, HIDDEN / 128);
        gemm_hmma<<<grid, 256, GEMM_SMEM>>>(ath, atl, woh, wol, nullptr, out, HIDDEN);
    }
}